// round 4
// baseline (speedup 1.0000x reference)
#include <cuda_runtime.h>
#include <math.h>

// RMSPELoss R4: filter-on-load. Labels are only tested ==1 (4 hits per 181),
// so don't stage them — scan the int4 stream and record hit columns via a
// tiny smem counter. Deletes the STS/LDS round-trip and the ballot chains.

#define BATCH 131072
#define NC 181
#define ROWS_PER_BLOCK 8
#define THREADS 256
#define NBLOCKS (BATCH / ROWS_PER_BLOCK)               // 16384
#define INTS_PER_BLOCK (NC * ROWS_PER_BLOCK)           // 1448 ints = 5792 B (16B-aligned)
#define INT4_PER_BLOCK (INTS_PER_BLOCK / 4)            // 362
#define PI_F 3.14159265358979323846f
#define TWOPI_F 6.283185307179586f
#define INV_TWOPI_F 0.15915494309189535f

__device__ double   g_acc;   // zeroed at load; reset by last block each call
__device__ unsigned g_done;  // completion counter, ditto

#define PK(a,b,c,d) ((unsigned)(a) | ((unsigned)(b)<<8) | ((unsigned)(c)<<16) | ((unsigned)(d)<<24))
__constant__ unsigned c_perm_packed[24] = {
    PK(0,1,2,3),PK(0,1,3,2),PK(0,2,1,3),PK(0,2,3,1),PK(0,3,1,2),PK(0,3,2,1),
    PK(1,0,2,3),PK(1,0,3,2),PK(1,2,0,3),PK(1,2,3,0),PK(1,3,0,2),PK(1,3,2,0),
    PK(2,0,1,3),PK(2,0,3,1),PK(2,1,0,3),PK(2,1,3,0),PK(2,3,0,1),PK(2,3,1,0),
    PK(3,0,1,2),PK(3,0,2,1),PK(3,1,0,2),PK(3,1,2,0),PK(3,2,0,1),PK(3,2,1,0)
};

__global__ __launch_bounds__(THREADS, 8)
void rmspe_main(const float* __restrict__ logits, const int* __restrict__ labels,
                float* __restrict__ out) {
    __shared__ float    s_doa[ROWS_PER_BLOCK][4];
    __shared__ int      s_idx[ROWS_PER_BLOCK][4];
    __shared__ int      s_cnt[ROWS_PER_BLOCK];
    __shared__ float    s_cost[ROWS_PER_BLOCK][16];
    __shared__ float    s_part[ROWS_PER_BLOCK];
    __shared__ unsigned s_perm[24];

    const int tid  = threadIdx.x;
    const int lane = tid & 31;
    const int w    = tid >> 5;                       // warp = row within block
    const long row0 = (long)blockIdx.x * ROWS_PER_BLOCK;

    if (tid < ROWS_PER_BLOCK) s_cnt[tid] = 0;
    if (tid < ROWS_PER_BLOCK * 4) {                  // logits load in the same wave
        int r = tid >> 2, k = tid & 3;
        s_doa[r][k] = logits[(row0 + r) * NC + k];
    }
    if (tid < 24) s_perm[tid] = c_perm_packed[tid];
    __syncthreads();

    // ---- phase 1: filter-on-load int4 scan of the block's label region ----
    const int4* g4 = reinterpret_cast<const int4*>(labels + row0 * NC);
    #pragma unroll
    for (int it = 0; it < 2; it++) {
        int i = tid + it * THREADS;
        if (i < INT4_PER_BLOCK) {
            int4 v = g4[i];
            int linear = i * 4;
            if (v.x == 1) { int r = linear / NC;       int p = atomicAdd(&s_cnt[r], 1); if (p < 4) s_idx[r][p] = linear - r * NC; }
            if (v.y == 1) { int r = (linear + 1) / NC; int p = atomicAdd(&s_cnt[r], 1); if (p < 4) s_idx[r][p] = (linear + 1) - r * NC; }
            if (v.z == 1) { int r = (linear + 2) / NC; int p = atomicAdd(&s_cnt[r], 1); if (p < 4) s_idx[r][p] = (linear + 2) - r * NC; }
            if (v.w == 1) { int r = (linear + 3) / NC; int p = atomicAdd(&s_cnt[r], 1); if (p < 4) s_idx[r][p] = (linear + 3) - r * NC; }
        }
    }
    __syncthreads();

    // ---- phase 2: 16 lanes of warp w compute row w's 4x4 cost matrix ----
    if (lane < 16) {
        int i = lane >> 2, j = lane & 3;
        float a = s_doa[w][i];
        float b = ((float)s_idx[w][j] - 90.0f) * (PI_F / 180.0f);
        float x = a - b + PI_F;
        float m = x - TWOPI_F * floorf(x * INV_TWOPI_F);  // mod(x, 2pi) in [0,2pi)
        float d = m - PI_F;
        s_cost[w][lane] = d * d;
    }
    __syncwarp();

    // ---- phase 3: 24 lanes each evaluate one permutation; warp-min ----
    float t = 3.402823466e+38f;
    if (lane < 24) {
        unsigned p = s_perm[lane];
        t = s_cost[w][      (p        & 0xffu)]
          + s_cost[w][ 4 + ((p >>  8) & 0xffu)]
          + s_cost[w][ 8 + ((p >> 16) & 0xffu)]
          + s_cost[w][12 + ( p >> 24        )];
    }
    #pragma unroll
    for (int off = 16; off; off >>= 1)
        t = fminf(t, __shfl_xor_sync(0xffffffffu, t, off));
    if (lane == 0) s_part[w] = sqrtf(t * 0.25f);
    __syncthreads();

    // ---- phase 4: block reduce + last-block epilogue ----
    if (tid == 0) {
        float x = 0.0f;
        #pragma unroll
        for (int r = 0; r < ROWS_PER_BLOCK; r++) x += s_part[r];
        atomicAdd(&g_acc, (double)x);
        __threadfence();
        unsigned prev = atomicAdd(&g_done, 1u);
        if (prev == NBLOCKS - 1) {
            __threadfence();
            double total = *((volatile double*)&g_acc);
            out[0] = (float)(total / (double)BATCH);
            g_acc  = 0.0;   // deterministic state for the next graph replay
            g_done = 0u;
        }
    }
}

extern "C" void kernel_launch(void* const* d_in, const int* in_sizes, int n_in,
                              void* d_out, int out_size) {
    const float* logits = (const float*)d_in[0];
    const int*   labels = (const int*)d_in[1];
    float* out = (float*)d_out;

    rmspe_main<<<NBLOCKS, THREADS>>>(logits, labels, out);
}

// round 5
// speedup vs baseline: 1.2600x; 1.2600x over previous
#include <cuda_runtime.h>
#include <math.h>

// RMSPELoss R5: decoupled. Kernel 1 = pure 94.9MB label stream (MLP=4 LDG.128
// per thread, rare-hit scatter via spread global atomics). Kernel 2 = one
// thread per row: 4x4 circular cost + 24-perm min in registers, reduce.

#define BATCH 131072
#define NC 181
#define PI_F 3.14159265358979323846f
#define TWOPI_F 6.283185307179586f
#define INV_TWOPI_F 0.15915494309189535f

#define TOTAL_INT4 (BATCH * NC / 4)        // 5,931,008
#define SCAN_THREADS 256
#define SCAN_UNROLL 4
#define SCAN_BLOCKS (TOTAL_INT4 / (SCAN_THREADS * SCAN_UNROLL))   // 5792, exact
#define SCAN_STRIDE (SCAN_BLOCKS * SCAN_THREADS)                  // 1,482,752

#define FIN_THREADS 256
#define FIN_BLOCKS (BATCH / FIN_THREADS)   // 512

__device__ double   g_acc;                 // zero-init; reset by epilogue
__device__ unsigned g_done;                // zero-init; reset by epilogue
__device__ int      g_cnt[BATCH];          // zero-init; reset by finish kernel
__device__ __align__(16) int g_idx[BATCH * 4];

// ---------------- kernel 1: streaming scan ----------------
__global__ __launch_bounds__(SCAN_THREADS)
void rmspe_scan(const int* __restrict__ labels) {
    const int t = blockIdx.x * SCAN_THREADS + threadIdx.x;
    const int4* __restrict__ g4 = reinterpret_cast<const int4*>(labels);

    // front-batched independent loads: MLP = 4
    int4 v[SCAN_UNROLL];
    #pragma unroll
    for (int j = 0; j < SCAN_UNROLL; j++)
        v[j] = g4[t + j * SCAN_STRIDE];

    #pragma unroll
    for (int j = 0; j < SCAN_UNROLL; j++) {
        int4 x = v[j];
        if ((x.x | x.y | x.z | x.w) != 0) {        // rare (~8.5% of int4s)
            int linear = (t + j * SCAN_STRIDE) * 4;
            int vals[4] = {x.x, x.y, x.z, x.w};
            #pragma unroll
            for (int k = 0; k < 4; k++) {
                if (vals[k] == 1) {
                    int l = linear + k;
                    int r = l / NC;                 // mul-shift by constant
                    int c = l - r * NC;
                    int p = atomicAdd(&g_cnt[r], 1);
                    if (p < 4) g_idx[r * 4 + p] = c;
                }
            }
        }
    }
}

// ---------------- kernel 2: per-row assignment min + reduce ----------------
__global__ __launch_bounds__(FIN_THREADS)
void rmspe_finish(const float* __restrict__ logits, float* __restrict__ out) {
    __shared__ float s_warp[FIN_THREADS / 32];

    const int row  = blockIdx.x * FIN_THREADS + threadIdx.x;
    const int lane = threadIdx.x & 31;
    const int w    = threadIdx.x >> 5;

    // coalesced 16B read of this row's 4 one-positions; reset counter for replay
    int4 id = reinterpret_cast<const int4*>(g_idx)[row];
    g_cnt[row] = 0;

    const float* lp = logits + (long)row * NC;
    float doa[4] = {lp[0], lp[1], lp[2], lp[3]};
    int   idx[4] = {id.x, id.y, id.z, id.w};

    float cost[4][4];
    #pragma unroll
    for (int i = 0; i < 4; i++) {
        #pragma unroll
        for (int j = 0; j < 4; j++) {
            float b = ((float)idx[j] - 90.0f) * (PI_F / 180.0f);
            float x = doa[i] - b + PI_F;
            float m = x - TWOPI_F * floorf(x * INV_TWOPI_F);  // mod in [0,2pi)
            float d = m - PI_F;
            cost[i][j] = d * d;
        }
    }

    float best = 3.402823466e+38f;
    #define P4(a,b,c,d) best = fminf(best, cost[0][a] + cost[1][b] + cost[2][c] + cost[3][d]);
    P4(0,1,2,3) P4(0,1,3,2) P4(0,2,1,3) P4(0,2,3,1) P4(0,3,1,2) P4(0,3,2,1)
    P4(1,0,2,3) P4(1,0,3,2) P4(1,2,0,3) P4(1,2,3,0) P4(1,3,0,2) P4(1,3,2,0)
    P4(2,0,1,3) P4(2,0,3,1) P4(2,1,0,3) P4(2,1,3,0) P4(2,3,0,1) P4(2,3,1,0)
    P4(3,0,1,2) P4(3,0,2,1) P4(3,1,0,2) P4(3,1,2,0) P4(3,2,0,1) P4(3,2,1,0)
    #undef P4

    float rmse = sqrtf(best * 0.25f);

    // warp reduce -> smem -> warp0 -> one double RED per block
    #pragma unroll
    for (int off = 16; off; off >>= 1)
        rmse += __shfl_down_sync(0xffffffffu, rmse, off);
    if (lane == 0) s_warp[w] = rmse;
    __syncthreads();

    if (threadIdx.x == 0) {
        float x = 0.0f;
        #pragma unroll
        for (int i = 0; i < FIN_THREADS / 32; i++) x += s_warp[i];
        atomicAdd(&g_acc, (double)x);
        __threadfence();
        unsigned prev = atomicAdd(&g_done, 1u);
        if (prev == FIN_BLOCKS - 1) {
            __threadfence();
            double total = *((volatile double*)&g_acc);
            out[0] = (float)(total / (double)BATCH);
            g_acc  = 0.0;     // deterministic state for next graph replay
            g_done = 0u;
        }
    }
}

extern "C" void kernel_launch(void* const* d_in, const int* in_sizes, int n_in,
                              void* d_out, int out_size) {
    const float* logits = (const float*)d_in[0];
    const int*   labels = (const int*)d_in[1];
    float* out = (float*)d_out;

    rmspe_scan<<<SCAN_BLOCKS, SCAN_THREADS>>>(labels);
    rmspe_finish<<<FIN_BLOCKS, FIN_THREADS>>>(logits, out);
}

// round 6
// speedup vs baseline: 1.7025x; 1.3513x over previous
#include <cuda_runtime.h>
#include <math.h>
#include <float.h>

// RMSPELoss R6: scan uses fire-and-forget REDG bitmap (no atomic return
// dependency); finish uses 4 lanes/row (full occupancy, coalesced gather),
// register-only cost/perm evaluation via switch(q).

#define BATCH 131072
#define NC 181
#define PI_F 3.14159265358979323846f
#define TWOPI_F 6.283185307179586f
#define INV_TWOPI_F 0.15915494309189535f

#define TOTAL_INT4 (BATCH * NC / 4)                    // 5,931,008
#define SCAN_THREADS 256
#define SCAN_UNROLL 8
#define SCAN_BLOCKS (TOTAL_INT4 / (SCAN_THREADS * SCAN_UNROLL))   // 2896, exact
#define SCAN_STRIDE (SCAN_BLOCKS * SCAN_THREADS)                  // 741,376

#define FIN_THREADS 256
#define FIN_BLOCKS (BATCH * 4 / FIN_THREADS)           // 2048

__device__ double   g_acc;    // zero-init; reset by epilogue each call
__device__ unsigned g_done;   // zero-init; reset by epilogue each call
// 4 words/row (word 3 always 0) -> 16B-aligned coalesced access. Zero-init;
// finish re-zeroes every word it reads, so each graph replay starts clean.
__device__ __align__(16) unsigned long long g_bits[BATCH * 4];

// ---------------- kernel 1: pure streaming scan ----------------
__global__ __launch_bounds__(SCAN_THREADS)
void rmspe_scan(const int* __restrict__ labels) {
    const int t = blockIdx.x * SCAN_THREADS + threadIdx.x;
    const int4* __restrict__ g4 = reinterpret_cast<const int4*>(labels);

    // front-batched independent loads: MLP = 8, perfectly coalesced
    int4 v[SCAN_UNROLL];
    #pragma unroll
    for (int j = 0; j < SCAN_UNROLL; j++)
        v[j] = __ldcs(&g4[t + j * SCAN_STRIDE]);

    #pragma unroll
    for (int j = 0; j < SCAN_UNROLL; j++) {
        int4 x = v[j];
        if ((x.x | x.y | x.z | x.w) != 0) {            // rare (~8.5% of int4s)
            int linear = (t + j * SCAN_STRIDE) * 4;
            int vals[4] = {x.x, x.y, x.z, x.w};
            #pragma unroll
            for (int k = 0; k < 4; k++) {
                if (vals[k] == 1) {
                    int l = linear + k;
                    int r = l / NC;                    // mul-shift by constant
                    int c = l - r * NC;
                    // result unused -> REDG (fire-and-forget, no return dep)
                    atomicOr(&g_bits[r * 4 + (c >> 6)], 1ull << (c & 63));
                }
            }
        }
    }
}

// ---------------- kernel 2: 4 lanes per row ----------------
__global__ __launch_bounds__(FIN_THREADS)
void rmspe_finish(const float* __restrict__ logits, float* __restrict__ out) {
    __shared__ float s_warp[FIN_THREADS / 32];

    const int gtid = blockIdx.x * FIN_THREADS + threadIdx.x;
    const int row  = gtid >> 2;
    const int q    = gtid & 3;                 // quad lane = word index / doa index
    const int lane = threadIdx.x & 31;
    const int base = lane & ~3;

    // coalesced: one 8B bitmap word + one logits float per lane
    unsigned long long w = g_bits[gtid];
    g_bits[gtid] = 0ull;                        // reset for next graph replay
    float f = logits[(long)row * NC + q];

    // quad-exclusive prefix of set-bit counts
    int c  = __popcll(w);
    int c0 = __shfl_sync(0xffffffffu, c, base);
    int c1 = __shfl_sync(0xffffffffu, c, base + 1);
    int c2 = __shfl_sync(0xffffffffu, c, base + 2);
    int s  = (q > 0 ? c0 : 0) + (q > 1 ? c1 : 0) + (q > 2 ? c2 : 0);

    // pack this word's columns into 16-bit slots, then OR-merge across quad
    unsigned long long packed = 0ull, ww = w;
    while (ww) {
        int b = __ffsll((long long)ww) - 1;
        ww &= ww - 1;
        packed |= (unsigned long long)(q * 64 + b) << (16 * s);
        s++;
    }
    packed |= __shfl_xor_sync(0xffffffffu, packed, 1);
    packed |= __shfl_xor_sync(0xffffffffu, packed, 2);

    // broadcast the 4 doa values within the quad
    float doa[4];
    doa[0] = __shfl_sync(0xffffffffu, f, base);
    doa[1] = __shfl_sync(0xffffffffu, f, base + 1);
    doa[2] = __shfl_sync(0xffffffffu, f, base + 2);
    doa[3] = __shfl_sync(0xffffffffu, f, base + 3);

    float ang[4];
    #pragma unroll
    for (int j = 0; j < 4; j++)
        ang[j] = ((float)((packed >> (16 * j)) & 0xffffu) - 90.0f) * (PI_F / 180.0f);

    float cost[4][4];
    #pragma unroll
    for (int i = 0; i < 4; i++) {
        #pragma unroll
        for (int j = 0; j < 4; j++) {
            float x = doa[i] - ang[j] + PI_F;
            float m = x - TWOPI_F * floorf(x * INV_TWOPI_F);  // mod in [0,2pi)
            float d = m - PI_F;
            cost[i][j] = d * d;
        }
    }

    // 6 perms per lane, constant indices only (no local-memory spill)
    float best = FLT_MAX;
    #define PM(a,b,cc,d) best = fminf(best, cost[0][a] + cost[1][b] + cost[2][cc] + cost[3][d]);
    switch (q) {
        case 0: PM(0,1,2,3) PM(0,1,3,2) PM(0,2,1,3) PM(0,2,3,1) PM(0,3,1,2) PM(0,3,2,1) break;
        case 1: PM(1,0,2,3) PM(1,0,3,2) PM(1,2,0,3) PM(1,2,3,0) PM(1,3,0,2) PM(1,3,2,0) break;
        case 2: PM(2,0,1,3) PM(2,0,3,1) PM(2,1,0,3) PM(2,1,3,0) PM(2,3,0,1) PM(2,3,1,0) break;
        case 3: PM(3,0,1,2) PM(3,0,2,1) PM(3,1,0,2) PM(3,1,2,0) PM(3,2,0,1) PM(3,2,1,0) break;
    }
    #undef PM
    best = fminf(best, __shfl_xor_sync(0xffffffffu, best, 1));
    best = fminf(best, __shfl_xor_sync(0xffffffffu, best, 2));

    float rmse = (q == 0) ? sqrtf(best * 0.25f) : 0.0f;

    // warp sum -> smem -> thread0 -> one double RED per block
    #pragma unroll
    for (int off = 16; off; off >>= 1)
        rmse += __shfl_down_sync(0xffffffffu, rmse, off);
    if (lane == 0) s_warp[threadIdx.x >> 5] = rmse;
    __syncthreads();

    if (threadIdx.x == 0) {
        float x = 0.0f;
        #pragma unroll
        for (int i = 0; i < FIN_THREADS / 32; i++) x += s_warp[i];
        atomicAdd(&g_acc, (double)x);
        __threadfence();
        unsigned prev = atomicAdd(&g_done, 1u);
        if (prev == FIN_BLOCKS - 1) {
            __threadfence();
            double total = *((volatile double*)&g_acc);
            out[0] = (float)(total / (double)BATCH);
            g_acc  = 0.0;     // deterministic state for next graph replay
            g_done = 0u;
        }
    }
}

extern "C" void kernel_launch(void* const* d_in, const int* in_sizes, int n_in,
                              void* d_out, int out_size) {
    const float* logits = (const float*)d_in[0];
    const int*   labels = (const int*)d_in[1];
    float* out = (float*)d_out;

    rmspe_scan<<<SCAN_BLOCKS, SCAN_THREADS>>>(labels);
    rmspe_finish<<<FIN_BLOCKS, FIN_THREADS>>>(logits, out);
}

// round 7
// speedup vs baseline: 1.9267x; 1.1317x over previous
#include <cuda_runtime.h>
#include <math.h>
#include <float.h>

// RMSPELoss R7: scan (REDG bitmap, near stream ceiling) unchanged except
// bitmap packs 3 words/row. Finish: 1 thread/row, MLP=7 front-batched loads,
// register-only bit extraction (4x pop-lowest across 3 words) + 24-perm min.

#define BATCH 131072
#define NC 181
#define PI_F 3.14159265358979323846f
#define TWOPI_F 6.283185307179586f
#define INV_TWOPI_F 0.15915494309189535f

#define TOTAL_INT4 (BATCH * NC / 4)                    // 5,931,008
#define SCAN_THREADS 256
#define SCAN_UNROLL 8
#define SCAN_BLOCKS (TOTAL_INT4 / (SCAN_THREADS * SCAN_UNROLL))   // 2896, exact
#define SCAN_STRIDE (SCAN_BLOCKS * SCAN_THREADS)                  // 741,376

#define FIN_THREADS 256
#define FIN_BLOCKS (BATCH / FIN_THREADS)               // 512

__device__ double   g_acc;    // zero-init; reset by epilogue each call
__device__ unsigned g_done;   // zero-init; reset by epilogue each call
// 3 x 64-bit words per row (192 bits >= 181). Zero-init; finish re-zeroes
// every word it reads, so each graph replay starts clean.
__device__ unsigned long long g_bits[BATCH * 3];

// ---------------- kernel 1: pure streaming scan ----------------
__global__ __launch_bounds__(SCAN_THREADS)
void rmspe_scan(const int* __restrict__ labels) {
    const int t = blockIdx.x * SCAN_THREADS + threadIdx.x;
    const int4* __restrict__ g4 = reinterpret_cast<const int4*>(labels);

    // front-batched independent loads: MLP = 8, perfectly coalesced
    int4 v[SCAN_UNROLL];
    #pragma unroll
    for (int j = 0; j < SCAN_UNROLL; j++)
        v[j] = __ldcs(&g4[t + j * SCAN_STRIDE]);

    #pragma unroll
    for (int j = 0; j < SCAN_UNROLL; j++) {
        int4 x = v[j];
        if ((x.x | x.y | x.z | x.w) != 0) {            // rare (~8.5% of int4s)
            int linear = (t + j * SCAN_STRIDE) * 4;
            int vals[4] = {x.x, x.y, x.z, x.w};
            #pragma unroll
            for (int k = 0; k < 4; k++) {
                if (vals[k] == 1) {
                    int l = linear + k;
                    int r = l / NC;                    // mul-shift by constant
                    int c = l - r * NC;
                    // result unused -> REDG (fire-and-forget, no return dep)
                    atomicOr(&g_bits[r * 3 + (c >> 6)], 1ull << (c & 63));
                }
            }
        }
    }
}

// pop the lowest set bit across a 192-bit value in 3 registers
__device__ __forceinline__ int pop_lowest(unsigned long long& w0,
                                          unsigned long long& w1,
                                          unsigned long long& w2) {
    if (w0) { int b = __ffsll((long long)w0) - 1; w0 &= w0 - 1; return b; }
    if (w1) { int b = __ffsll((long long)w1) - 1; w1 &= w1 - 1; return 64 + b; }
    {        int b = __ffsll((long long)w2) - 1; w2 &= w2 - 1; return 128 + b; }
}

// ---------------- kernel 2: one thread per row ----------------
__global__ __launch_bounds__(FIN_THREADS)
void rmspe_finish(const float* __restrict__ logits, float* __restrict__ out) {
    __shared__ float s_warp[FIN_THREADS / 32];

    const int row  = blockIdx.x * FIN_THREADS + threadIdx.x;
    const int lane = threadIdx.x & 31;

    // ---- one latency wave: 3 bitmap words + 4 logits scalars (MLP=7) ----
    unsigned long long* bp = &g_bits[row * 3];
    unsigned long long w0 = bp[0];
    unsigned long long w1 = bp[1];
    unsigned long long w2 = bp[2];
    const float* lp = logits + (long)row * NC;
    float d0 = lp[0], d1 = lp[1], d2 = lp[2], d3 = lp[3];

    // reset bitmap for the next graph replay (fire-and-forget stores)
    bp[0] = 0ull; bp[1] = 0ull; bp[2] = 0ull;

    // ---- extract the 4 one-positions into named registers ----
    int i0 = pop_lowest(w0, w1, w2);
    int i1 = pop_lowest(w0, w1, w2);
    int i2 = pop_lowest(w0, w1, w2);
    int i3 = pop_lowest(w0, w1, w2);

    float ang[4];
    ang[0] = ((float)i0 - 90.0f) * (PI_F / 180.0f);
    ang[1] = ((float)i1 - 90.0f) * (PI_F / 180.0f);
    ang[2] = ((float)i2 - 90.0f) * (PI_F / 180.0f);
    ang[3] = ((float)i3 - 90.0f) * (PI_F / 180.0f);
    float doa[4] = {d0, d1, d2, d3};

    float cost[4][4];
    #pragma unroll
    for (int i = 0; i < 4; i++) {
        #pragma unroll
        for (int j = 0; j < 4; j++) {
            float x = doa[i] - ang[j] + PI_F;
            float m = x - TWOPI_F * floorf(x * INV_TWOPI_F);  // mod in [0,2pi)
            float d = m - PI_F;
            cost[i][j] = d * d;
        }
    }

    float best = FLT_MAX;
    #define P4(a,b,c,d) best = fminf(best, cost[0][a] + cost[1][b] + cost[2][c] + cost[3][d]);
    P4(0,1,2,3) P4(0,1,3,2) P4(0,2,1,3) P4(0,2,3,1) P4(0,3,1,2) P4(0,3,2,1)
    P4(1,0,2,3) P4(1,0,3,2) P4(1,2,0,3) P4(1,2,3,0) P4(1,3,0,2) P4(1,3,2,0)
    P4(2,0,1,3) P4(2,0,3,1) P4(2,1,0,3) P4(2,1,3,0) P4(2,3,0,1) P4(2,3,1,0)
    P4(3,0,1,2) P4(3,0,2,1) P4(3,1,0,2) P4(3,1,2,0) P4(3,2,0,1) P4(3,2,1,0)
    #undef P4

    float rmse = sqrtf(best * 0.25f);

    // ---- warp sum -> smem -> thread0 -> one double RED per block ----
    #pragma unroll
    for (int off = 16; off; off >>= 1)
        rmse += __shfl_down_sync(0xffffffffu, rmse, off);
    if (lane == 0) s_warp[threadIdx.x >> 5] = rmse;
    __syncthreads();

    if (threadIdx.x == 0) {
        float x = 0.0f;
        #pragma unroll
        for (int i = 0; i < FIN_THREADS / 32; i++) x += s_warp[i];
        atomicAdd(&g_acc, (double)x);
        __threadfence();
        unsigned prev = atomicAdd(&g_done, 1u);
        if (prev == FIN_BLOCKS - 1) {
            __threadfence();
            double total = *((volatile double*)&g_acc);
            out[0] = (float)(total / (double)BATCH);
            g_acc  = 0.0;     // deterministic state for next graph replay
            g_done = 0u;
        }
    }
}

extern "C" void kernel_launch(void* const* d_in, const int* in_sizes, int n_in,
                              void* d_out, int out_size) {
    const float* logits = (const float*)d_in[0];
    const int*   labels = (const int*)d_in[1];
    float* out = (float*)d_out;

    rmspe_scan<<<SCAN_BLOCKS, SCAN_THREADS>>>(labels);
    rmspe_finish<<<FIN_BLOCKS, FIN_THREADS>>>(logits, out);
}